// round 7
// baseline (speedup 1.0000x reference)
#include <cuda_runtime.h>
#include <math.h>

#define Lr 1024
#define Br 32
#define Dr 256
#define LAMf 0.2f
#define NR (Lr*Br)

// Scratch (device globals, zero-initialized). Batch-major r = b*Lr + i.
__device__ float g_K[NR*5];      // K[i, j=i+d-2], d=0..4
__device__ float g_S[NR];        // row sums of K
__device__ float g_E[NR];        // sum_d K*(1-cos)
__device__ int   g_cnt[Br];      // per-batch arrival counters (reset by epilogue)

// One kernel: band compute (4096 batch-pure blocks of 8 rows) + last-block epilogue per batch.
__global__ void __launch_bounds__(256) kall(const float* __restrict__ m1,
                                            const float* __restrict__ m2,
                                            const int* __restrict__ lengths,
                                            float* __restrict__ out) {
    __shared__ float sh_invn[20];    // [0,8): 1/||x_{i0+k}||, [8,20): 1/||y_{i0-2+k}||
    __shared__ int   sh_last;
    __shared__ float sh_invS[Lr];    // epilogue
    __shared__ float sh_t[Lr];
    __shared__ float sh_c[256];

    int tid  = threadIdx.x;
    int w    = tid >> 5, lane = tid & 31;
    int b    = blockIdx.x & 31;
    int i0   = (blockIdx.x >> 5) * 8;
    int l    = __ldg(lengths + b);
    int base = b * Lr;

    // ---- phase 1: shared inverse norms (8 m1 rows + 12 m2 rows, each computed once) ----
    for (int job = w; job < 20; job += 8) {
        int row; const float* src;
        if (job < 8) { row = i0 + job;           src = m1; }
        else         { row = i0 - 2 + (job - 8); src = m2; }
        float invn = 0.0f;
        if (row >= 0 && row < l) {
            const float4* p = (const float4*)(src + ((size_t)(row*Br + b)) * Dr);
            float4 a = p[lane], c = p[lane + 32];
            float ss = a.x*a.x + a.y*a.y + a.z*a.z + a.w*a.w
                     + c.x*c.x + c.y*c.y + c.z*c.z + c.w*c.w;
            #pragma unroll
            for (int o = 16; o; o >>= 1) ss += __shfl_xor_sync(0xffffffffu, ss, o);
            invn = 1.0f / fmaxf(sqrtf(ss), 1e-5f);
        }
        if (lane == 0) sh_invn[job] = invn;
    }
    __syncthreads();

    // ---- phase 2: 5 band dots per row, batched 5-way butterfly reduce ----
    int i = i0 + w;
    if (i < l) {
        const float4* xp = (const float4*)(m1 + ((size_t)(i*Br + b)) * Dr);
        float4 xa = xp[lane], xb = xp[lane + 32];
        float dots[5];
        #pragma unroll
        for (int d = 0; d < 5; d++) {
            int j = i + d - 2;
            float acc = 0.0f;
            if (j >= 0 && j < l) {
                const float4* yp = (const float4*)(m2 + ((size_t)(j*Br + b)) * Dr);
                float4 ya = yp[lane], yb = yp[lane + 32];
                acc = xa.x*ya.x + xa.y*ya.y + xa.z*ya.z + xa.w*ya.w
                    + xb.x*yb.x + xb.y*yb.y + xb.z*yb.z + xb.w*yb.w;
            }
            dots[d] = acc;
        }
        #pragma unroll
        for (int o = 16; o; o >>= 1) {
            #pragma unroll
            for (int d = 0; d < 5; d++)
                dots[d] += __shfl_xor_sync(0xffffffffu, dots[d], o);
        }
        if (lane == 0) {
            float invnx = sh_invn[w];
            float S = 0.0f, E = 0.0f, Ks[5];
            #pragma unroll
            for (int d = 0; d < 5; d++) {
                int j = i + d - 2;
                float Kv = 0.0f;
                if (j >= 0 && j < l) {
                    float Mv = 1.0f - dots[d] * invnx * sh_invn[8 + w + d];
                    Kv = expf(-LAMf * Mv);
                    E += Kv * Mv;
                }
                Ks[d] = Kv; S += Kv;
            }
            int rr = base + i;
            g_S[rr] = S; g_E[rr] = E;
            #pragma unroll
            for (int d = 0; d < 5; d++) g_K[rr*5 + d] = Ks[d];
        }
    }

    // ---- arrival counter (threadFenceReduction pattern) ----
    __threadfence();
    __syncthreads();
    if (tid == 0) {
        int old = atomicAdd(&g_cnt[b], 1);
        sh_last = (old == 127);
        if (old == 127) g_cnt[b] = 0;      // self-reset for next graph replay
    }
    __syncthreads();
    if (!sh_last) return;
    __threadfence();

    // ---- epilogue: whole batch b (256 threads) — t, band scatter, cost ----
    for (int idx = tid; idx < Lr; idx += 256)
        sh_invS[idx] = 1.0f / g_S[base + idx];     // inf for idx>=l, never used
    __syncthreads();

    for (int j = tid; j < Lr; j += 256) {
        float t = 1.0f;
        if (j < l) {
            t = 0.0f;
            #pragma unroll
            for (int dd = 0; dd < 5; dd++) {
                int ii = j + dd - 2;
                if (ii >= 0 && ii < l)
                    t += g_K[(size_t)(base + ii)*5 + (4 - dd)] * sh_invS[ii];
            }
        }
        sh_t[j] = t;
    }
    __syncthreads();

    float acc = 0.0f;
    for (int j = tid; j < l; j += 256) {
        float inv = sh_invS[j] / sh_t[j];
        acc += g_E[base + j] * inv;
        float* Po = out + (size_t)b * Lr * Lr + (size_t)j * Lr;
        #pragma unroll
        for (int d = 0; d < 5; d++) {
            int jj = j + d - 2;
            if (jj >= 0 && jj < l)
                Po[jj] = g_K[(size_t)(base + j)*5 + d] * sh_t[jj] * inv;
        }
    }
    sh_c[tid] = acc;
    __syncthreads();
    #pragma unroll
    for (int s = 128; s; s >>= 1) {
        if (tid < s) sh_c[tid] += sh_c[tid + s];
        __syncthreads();
    }
    if (tid == 0) out[(size_t)Br * Lr * Lr + b] = sh_c[0] / (float)l;
}

extern "C" void kernel_launch(void* const* d_in, const int* in_sizes, int n_in,
                              void* d_out, int out_size) {
    const float* m1      = (const float*)d_in[0];
    const float* m2      = (const float*)d_in[1];
    const int*   lengths = (const int*)d_in[2];
    float* out = (float*)d_out;

    kall<<<Br*128, 256>>>(m1, m2, lengths, out);   // 4096 blocks: band + in-kernel epilogue
}